// round 4
// baseline (speedup 1.0000x reference)
#include <cuda_runtime.h>
#include <math.h>

// DehLoss: O(n^2) pairwise Gaussian-kernel loss, n = 8192.
// R_i = g1_i + log(y_i), h = 1.3*n^-0.2, dr_ij = (R_i - R_j)/h
// Dk_j = sum_i d_i*phi(dr_ij);  LP_j = sum_i L_i*ndtr(dr_ij), L_i = exp(g2_i-g1_i)
// out = -(S1+S2+S3+S4)
//
// R4: 2 kernels total. Epilogue fused into pair kernel via last-block-done
// (deterministic: arrival order only selects WHICH block reduces; the reduce
// itself reads fixed memory in fixed order). JT=256 + dual accumulator chains
// for latency hiding. Pair math: f32x2 packed, AS 26.2.16 ndtr reusing phi,
// paired rcp, row compaction to d_j==1, hoisted 0.5*sum(L).

#define N      8192
#define SPLITS 16
#define CHUNK  (N / SPLITS)   // 512 columns per split
#define JT     256
#define GX     (N / JT)       // 32 static j-blocks
#define TOTAL_BLOCKS (GX * SPLITS)

typedef unsigned long long u64;

__device__ float4 g_A[N / 2];     // {Rh_2m, Rh_2m+1, d_2m, d_2m+1}
__device__ float2 g_Lp[N / 2];    // {L_2m, L_2m+1}
__device__ float  g_rowRh[N];     // compacted Rh_j for rows with d_j=1
__device__ int    g_M;            // number of compacted rows
__device__ float  g_Lsum;         // sum of L over all i
__device__ int    g_ctr;          // last-block-done counter (reset in prep)
__device__ float  g_partDk[SPLITS * N];
__device__ float  g_partLP[SPLITS * N];

__device__ __forceinline__ float ex2f_(float x) {
    float r; asm("ex2.approx.ftz.f32 %0, %1;" : "=f"(r) : "f"(x)); return r;
}
__device__ __forceinline__ float rcpf_(float x) {
    float r; asm("rcp.approx.ftz.f32 %0, %1;" : "=f"(r) : "f"(x)); return r;
}
__device__ __forceinline__ u64 pk2(float lo, float hi) {
    u64 r; asm("mov.b64 %0, {%1, %2};" : "=l"(r) : "f"(lo), "f"(hi)); return r;
}
__device__ __forceinline__ void upk2(u64 v, float& lo, float& hi) {
    asm("mov.b64 {%0, %1}, %2;" : "=f"(lo), "=f"(hi) : "l"(v));
}
__device__ __forceinline__ u64 fma2_(u64 a, u64 b, u64 c) {
    u64 d; asm("fma.rn.f32x2 %0, %1, %2, %3;" : "=l"(d) : "l"(a), "l"(b), "l"(c)); return d;
}
__device__ __forceinline__ u64 mul2_(u64 a, u64 b) {
    u64 d; asm("mul.rn.f32x2 %0, %1, %2;" : "=l"(d) : "l"(a), "l"(b)); return d;
}
__device__ __forceinline__ u64 add2_(u64 a, u64 b) {
    u64 d; asm("add.rn.f32x2 %0, %1, %2;" : "=l"(d) : "l"(a), "l"(b)); return d;
}

// Fused: per-i preprocessing + Lsum + deterministic compaction of d_j==1 rows.
__global__ void __launch_bounds__(1024) prep_kernel(const float* __restrict__ mz,
                                                    const float* __restrict__ y,
                                                    const float* __restrict__ delta,
                                                    float inv_h) {
    __shared__ int    cnt[1024];
    __shared__ double lred[1024];
    const int t = threadIdx.x;
    const int base = t * 8;
    if (t == 0) g_ctr = 0;

    float Rh[8]; int flags[8]; int c = 0; double ls = 0.0;
    #pragma unroll
    for (int q = 0; q < 8; ++q) {
        int j = base + q;
        float g1 = mz[2 * j], g2 = mz[2 * j + 1];
        float R = g1 + logf(y[j]);
        Rh[q] = R * inv_h;
        float d = delta[j];
        float L = expf(g2 - g1);
        ls += (double)L;
        flags[q] = d > 0.5f;
        c += flags[q];
        if (q & 1) {
            float4 a; a.x = Rh[q - 1]; a.y = Rh[q];
            a.z = (float)flags[q - 1]; a.w = (float)flags[q];
            g_A[j >> 1] = a;
            float g2p = mz[2 * (j - 1) + 1], g1p = mz[2 * (j - 1)];
            g_Lp[j >> 1] = make_float2(expf(g2p - g1p), L);
        }
    }
    cnt[t] = c; lred[t] = ls;
    __syncthreads();
    for (int off = 1; off < 1024; off <<= 1) {
        int v = (t >= off) ? cnt[t - off] : 0;
        __syncthreads();
        cnt[t] += v;
        __syncthreads();
    }
    int pos = cnt[t] - c;
    #pragma unroll
    for (int q = 0; q < 8; ++q) {
        if (flags[q]) g_rowRh[pos++] = Rh[q];
    }
    if (t == 1023) g_M = cnt[1023];
    for (int s = 512; s > 0; s >>= 1) {
        if (t < s) lred[t] += lred[t + s];
        __syncthreads();
    }
    if (t == 0) g_Lsum = (float)lred[0];
}

#define PAIR_BODY(K_, dkacc, lpacc)                                    \
    {                                                                   \
        float4 a = shA[K_];                                             \
        float2 L = shL[K_];                                             \
        u64 Rh2 = pk2(a.x, a.y);                                        \
        u64 d2  = pk2(a.z, a.w);                                        \
        u64 L2  = pk2(L.x, L.y);                                        \
        u64 dr2 = add2_(Rh2, nRhj2);                                    \
        u64 e2  = fma2_(mul2_(dr2, C1_2), dr2, C2_2);                   \
        float elo, ehi; upk2(e2, elo, ehi);                             \
        u64 phi2 = pk2(ex2f_(elo), ex2f_(ehi));                         \
        dkacc = fma2_(d2, phi2, dkacc);                                 \
        u64 den2 = fma2_(dr2 & AMSK, PP2, ONE2);                        \
        float dlo, dhi; upk2(den2, dlo, dhi);                           \
        float rr = rcpf_(dlo * dhi);                                    \
        u64 t2 = pk2(rr * dhi, rr * dlo);                               \
        u64 p2 = fma2_(t2, NA3_2, NA2_2);                               \
        p2 = fma2_(t2, p2, NA1_2);                                      \
        p2 = mul2_(t2, p2);                                             \
        u64 u2 = fma2_(phi2, p2, HALF2);                                \
        lpacc = fma2_(L2, u2 | (dr2 & SMSK), lpacc);                    \
    }

__global__ void __launch_bounds__(JT) pair_kernel(const float* __restrict__ mz,
                                                  float h, float* __restrict__ out) {
    __shared__ float4 shA[CHUNK / 2];
    __shared__ float2 shL[CHUNK / 2];
    __shared__ double red[JT];
    __shared__ int    lastFlag;

    const int tid = threadIdx.x;
    const int M = g_M;
    const bool active = (int)(blockIdx.x * JT) < M;

    if (active) {
        const int c  = blockIdx.x * JT + tid;
        const int cc = min(c, M - 1);
        const int base2 = blockIdx.y * (CHUNK / 2);

        for (int k = tid; k < CHUNK / 2; k += JT) {
            shA[k] = g_A[base2 + k];
            shL[k] = g_Lp[base2 + k];
        }
        const float Rhj = g_rowRh[cc];
        __syncthreads();

        // C1 = -0.5*log2(e), C2 = log2(1/sqrt(2*pi)); AS 26.2.16 coeffs negated.
        const u64 nRhj2 = pk2(-Rhj, -Rhj);
        const u64 C1_2  = pk2(-0.72134752044448170f, -0.72134752044448170f);
        const u64 C2_2  = pk2(-1.32574806473615923f, -1.32574806473615923f);
        const u64 PP2   = pk2(0.33267f, 0.33267f);
        const u64 ONE2  = pk2(1.0f, 1.0f);
        const u64 HALF2 = pk2(0.5f, 0.5f);
        const u64 NA1_2 = pk2(-0.4361836f, -0.4361836f);
        const u64 NA2_2 = pk2( 0.1201676f,  0.1201676f);
        const u64 NA3_2 = pk2(-0.9372980f, -0.9372980f);
        const u64 AMSK  = 0x7FFFFFFF7FFFFFFFULL;
        const u64 SMSK  = 0x8000000080000000ULL;

        u64 dk2a = 0ULL, lp2a = 0ULL;   // two independent chains
        u64 dk2b = 0ULL, lp2b = 0ULL;

        #pragma unroll 4
        for (int k = 0; k < CHUNK / 2; k += 2) {
            PAIR_BODY(k,     dk2a, lp2a);
            PAIR_BODY(k + 1, dk2b, lp2b);
        }

        float dka, dkb, lpa, lpb, dkc, dkd, lpc, lpd;
        upk2(dk2a, dka, dkb); upk2(dk2b, dkc, dkd);
        upk2(lp2a, lpa, lpb); upk2(lp2b, lpc, lpd);
        if (c < M) {
            g_partDk[blockIdx.y * N + c] = (dka + dkb) + (dkc + dkd);
            g_partLP[blockIdx.y * N + c] = (lpa + lpb) + (lpc + lpd);
        }
    }

    // ---- last-block-done: the final arriving block reduces everything ----
    __threadfence();
    if (tid == 0) {
        int prev = atomicAdd(&g_ctr, 1);
        lastFlag = (prev == TOTAL_BLOCKS - 1);
    }
    __syncthreads();
    if (!lastFlag) return;

    const float Lsum   = g_Lsum;
    const float inv_nh = 1.0f / ((float)N * h);
    const float invn   = 1.0f / (float)N;
    double acc = 0.0;

    // S1 + S2: d_j * (g2_j - R_j) over all j
    for (int j = tid; j < N; j += JT) {
        float4 a = g_A[j >> 1];
        float Rh = (j & 1) ? a.y : a.x;
        float d  = (j & 1) ? a.w : a.z;
        float g2 = mz[2 * j + 1];
        acc += (double)(d * (g2 - Rh * h));
    }
    // S3 + S4 over compacted rows
    for (int c = tid; c < M; c += JT) {
        float dk = 0.0f, lp = 0.0f;
        #pragma unroll
        for (int s2 = 0; s2 < SPLITS; ++s2) {
            dk += g_partDk[s2 * N + c];
            lp += g_partLP[s2 * N + c];
        }
        float Dk = dk * inv_nh;
        float LP = (lp + 0.5f * Lsum) * invn;
        acc += (double)(logf(Dk + 1e-15f) - logf(LP + 1e-15f));
    }
    red[tid] = acc;
    __syncthreads();
    for (int s = JT / 2; s > 0; s >>= 1) {
        if (tid < s) red[tid] += red[tid + s];
        __syncthreads();
    }
    if (tid == 0) out[0] = (float)(-red[0] / (double)N);
}

extern "C" void kernel_launch(void* const* d_in, const int* in_sizes, int n_in,
                              void* d_out, int out_size) {
    const float* mz    = (const float*)d_in[0];
    const float* y     = (const float*)d_in[1];
    const float* delta = (const float*)d_in[2];
    float* out = (float*)d_out;

    const double hd = 1.3 * pow((double)N, -0.2);

    prep_kernel<<<1, 1024>>>(mz, y, delta, (float)(1.0 / hd));
    dim3 grid(GX, SPLITS);
    pair_kernel<<<grid, JT>>>(mz, (float)hd, out);
}